// round 12
// baseline (speedup 1.0000x reference)
#include <cuda_runtime.h>
#include <cstddef>
#include <cstdint>

#define SEQ 4096
#define DIM 1024
#define NHEAD 16
#define HDIM 64

__device__ float g_qkv[(size_t)SEQ * 3 * DIM];   // [T, 3D]
__device__ float g_y[(size_t)SEQ * DIM];         // [T, D]

__device__ __forceinline__ unsigned f2tf(float f) {
    unsigned u;
    asm("cvt.rna.tf32.f32 %0, %1;" : "=r"(u) : "f"(f));
    return u;
}

__device__ __forceinline__ void mma_tf32(float c[4], const unsigned a[4], const unsigned b[2]) {
    asm volatile(
        "mma.sync.aligned.m16n8k8.row.col.f32.tf32.tf32.f32 "
        "{%0,%1,%2,%3}, {%4,%5,%6,%7}, {%8,%9}, {%0,%1,%2,%3};"
        : "+f"(c[0]), "+f"(c[1]), "+f"(c[2]), "+f"(c[3])
        : "r"(a[0]), "r"(a[1]), "r"(a[2]), "r"(a[3]), "r"(b[0]), "r"(b[1]));
}

__device__ __forceinline__ uint32_t smem_u32(const void* p) {
    return (uint32_t)__cvta_generic_to_shared(p);
}

// One ldmatrix.x4 of b16 8x8 tiles == four 8x4 tf32 tiles; lane l gets, per
// matrix m, the tf32 at (row l/4, col l%4) -- exactly the mma frag layout.
#define LDSM4(r0, r1, r2, r3, addr)                                              \
    asm volatile("ldmatrix.sync.aligned.m8n8.x4.shared.b16 {%0,%1,%2,%3}, [%4];" \
                 : "=r"(r0), "=r"(r1), "=r"(r2), "=r"(r3) : "r"(addr))

// ===========================================================================
// TF32 GEMM "NT": C[m][n] = sum_k A[m][k] * B[n][k]
// 128x128 tile, KT=32, 256 threads (8 warps, 2m x 4n), warp tile 64x32.
// Double-buffered smem (tf32, stride 36 = odd quad stride -> LDSM clean);
// LDG prefetch held in regs across the mma loop; cvt.rna at STS time.
// Fragments via ldmatrix.x4: 6 LDSM per 16 mma.
// Dynamic smem: 2 bufs x (A+B) x 128*36*4B = 73728.
// ===========================================================================
#define GST 36
#define GTILE (128 * GST)          // floats per A (or B) buffer

__global__ __launch_bounds__(256) void gemm_tf32_lm(const float* __restrict__ A,
                                                    const float* __restrict__ B,
                                                    float* __restrict__ C,
                                                    int M, int N, int K)
{
    extern __shared__ float sm[];  // [2][A 128*36 | B 128*36]

    const int tid  = threadIdx.x;
    const int lane = tid & 31;
    const int warp = tid >> 5;
    const int wm = warp & 1;
    const int wn = warp >> 1;
    const int bm = blockIdx.y * 128;
    const int bn = blockIdx.x * 128;
    const int g = lane >> 2;
    const int r = lane & 3;

    const int srow = tid >> 3;     // 0..31 (+32/step)
    const int sc4  = tid & 7;

    float4 ra[4], rb[4];

    auto ldg = [&](int kt) {
        const float* Ap = A + (size_t)(bm + srow) * K + kt * 32 + sc4 * 4;
        const float* Bp = B + (size_t)(bn + srow) * K + kt * 32 + sc4 * 4;
#pragma unroll
        for (int t = 0; t < 4; ++t) {
            ra[t] = *(const float4*)(Ap + (size_t)(32 * t) * K);
            rb[t] = *(const float4*)(Bp + (size_t)(32 * t) * K);
        }
    };
    auto sts = [&](int buf) {
        float* Ad = sm + buf * 2 * GTILE;
        float* Bd = Ad + GTILE;
#pragma unroll
        for (int t = 0; t < 4; ++t) {
            int row = srow + 32 * t;
            *(uint4*)&Ad[row * GST + sc4 * 4] =
                make_uint4(f2tf(ra[t].x), f2tf(ra[t].y), f2tf(ra[t].z), f2tf(ra[t].w));
            *(uint4*)&Bd[row * GST + sc4 * 4] =
                make_uint4(f2tf(rb[t].x), f2tf(rb[t].y), f2tf(rb[t].z), f2tf(rb[t].w));
        }
    };

    float acc[4][4][4];
#pragma unroll
    for (int mi = 0; mi < 4; ++mi)
#pragma unroll
        for (int nj = 0; nj < 4; ++nj)
#pragma unroll
            for (int e = 0; e < 4; ++e) acc[mi][nj][e] = 0.f;

    // Per-lane ldmatrix base offsets (bytes) within a buffer.
    // A-type: bit3 of lane -> row+8, bit4 -> col+4.
    const uint32_t aoff =
        (uint32_t)(((wm * 64 + ((lane >> 3) & 1) * 8 + (lane & 7)) * GST + (lane >> 4) * 4) * 4);
    // B-type: bit3 -> col+4, bit4 -> next 8-row group (j+1).
    const uint32_t boff =
        (uint32_t)(((wn * 32 + (lane >> 4) * 8 + (lane & 7)) * GST + ((lane >> 3) & 1) * 4) * 4);

    const int nt = K / 32;
    ldg(0);
    sts(0);

    for (int kt = 0; kt < nt; ++kt) {
        __syncthreads();
        if (kt + 1 < nt) ldg(kt + 1);

        const int buf = kt & 1;
        const uint32_t Abase = smem_u32(sm + buf * 2 * GTILE);
        const uint32_t Bbase = Abase + GTILE * 4;

#pragma unroll
        for (int kk = 0; kk < 4; ++kk) {
            const uint32_t ko = kk * 32;   // 8 tf32 = 32 bytes
            unsigned af[4][4];
#pragma unroll
            for (int mi = 0; mi < 4; ++mi)
                LDSM4(af[mi][0], af[mi][1], af[mi][2], af[mi][3],
                      Abase + aoff + mi * (16 * GST * 4) + ko);
            unsigned bf[4][2];
            LDSM4(bf[0][0], bf[0][1], bf[1][0], bf[1][1], Bbase + boff + ko);
            LDSM4(bf[2][0], bf[2][1], bf[3][0], bf[3][1],
                  Bbase + boff + 16 * GST * 4 + ko);
#pragma unroll
            for (int mi = 0; mi < 4; ++mi)
#pragma unroll
                for (int nj = 0; nj < 4; ++nj)
                    mma_tf32(acc[mi][nj], af[mi], bf[nj]);
        }

        if (kt + 1 < nt) sts((kt + 1) & 1);
    }

    // Epilogue
#pragma unroll
    for (int mi = 0; mi < 4; ++mi) {
        int m = bm + wm * 64 + mi * 16 + g;
#pragma unroll
        for (int nj = 0; nj < 4; ++nj) {
            int n = bn + wn * 32 + nj * 8 + 2 * r;
            *(float2*)&C[(size_t)m * N + n]       = make_float2(acc[mi][nj][0], acc[mi][nj][1]);
            *(float2*)&C[(size_t)(m + 8) * N + n] = make_float2(acc[mi][nj][2], acc[mi][nj][3]);
        }
    }
}

// ===========================================================================
// TF32 flash attention, causal. Block = (64-query tile, head), 4 warps.
// K in Ks[token][d], V staged TRANSPOSED in Vt[d][token] (both stride 68 =
// odd quad stride) so K and V fragments load via ldmatrix.x4.
// Q frags register-resident (8 LDSM); P stays in registers via shuffles.
// ===========================================================================
__global__ __launch_bounds__(128) void attn_tf32(const float* __restrict__ qkv,
                                                 float* __restrict__ y)
{
    __shared__ unsigned Ks[64][68];
    __shared__ unsigned Vt[64][68];

    const int tid  = threadIdx.x;
    const int lane = tid & 31;
    const int warp = tid >> 5;
    const int qb = gridDim.x - 1 - blockIdx.x;   // heavy blocks first
    const int h  = blockIdx.y;
    const int g = lane >> 2;
    const int r = lane & 3;
    const int row0 = warp * 16;
    const float scale = 0.125f;

    const uint32_t Ksb = smem_u32(&Ks[0][0]);
    const uint32_t Vtb = smem_u32(&Vt[0][0]);
    // A-type lane offset (for Q fragments)
    const uint32_t qoff =
        (uint32_t)(((row0 + ((lane >> 3) & 1) * 8 + (lane & 7)) * 68 + (lane >> 4) * 4) * 4);
    // B-type lane offset (for K and V fragments)
    const uint32_t koff =
        (uint32_t)((((lane >> 4) * 8 + (lane & 7)) * 68 + ((lane >> 3) & 1) * 4) * 4);

    // ---- Stage Q (tf32) into Ks, pull fragments via ldmatrix ----
#pragma unroll
    for (int t = 0; t < 8; ++t) {
        int idx = tid + t * 128;
        int row = idx >> 4;
        int c4  = idx & 15;
        float4 v = *(const float4*)&qkv[(size_t)(qb * 64 + row) * (3 * DIM) + h * HDIM + c4 * 4];
        *(uint4*)&Ks[row][c4 * 4] = make_uint4(f2tf(v.x), f2tf(v.y), f2tf(v.z), f2tf(v.w));
    }
    __syncthreads();

    unsigned qf[8][4];
#pragma unroll
    for (int kk = 0; kk < 8; ++kk)
        LDSM4(qf[kk][0], qf[kk][1], qf[kk][2], qf[kk][3], Ksb + qoff + kk * 32);
    __syncthreads();

    float oacc[8][4];
#pragma unroll
    for (int j = 0; j < 8; ++j)
#pragma unroll
        for (int e = 0; e < 4; ++e) oacc[j][e] = 0.f;

    float m_lo = -1e30f, m_hi = -1e30f, l_lo = 0.f, l_hi = 0.f;

    for (int kt = 0; kt <= qb; ++kt) {
        // ---- Stage K [token][d] and V transposed [d][token] ----
#pragma unroll
        for (int t = 0; t < 8; ++t) {
            int idx = tid + t * 128;
            int row = idx >> 4;              // token within tile
            int c4  = idx & 15;              // d quad
            size_t base = (size_t)(kt * 64 + row) * (3 * DIM) + h * HDIM + c4 * 4;
            float4 kv = *(const float4*)&qkv[base + DIM];
            *(uint4*)&Ks[row][c4 * 4] = make_uint4(f2tf(kv.x), f2tf(kv.y), f2tf(kv.z), f2tf(kv.w));
            float4 vv = *(const float4*)&qkv[base + 2 * DIM];
            Vt[c4 * 4 + 0][row] = f2tf(vv.x);
            Vt[c4 * 4 + 1][row] = f2tf(vv.y);
            Vt[c4 * 4 + 2][row] = f2tf(vv.z);
            Vt[c4 * 4 + 3][row] = f2tf(vv.w);
        }
        __syncthreads();

        // ---- S = Q K^T ----
        float s[8][4];
#pragma unroll
        for (int j = 0; j < 8; ++j)
#pragma unroll
            for (int e = 0; e < 4; ++e) s[j][e] = 0.f;

#pragma unroll
        for (int kk = 0; kk < 8; ++kk) {
            unsigned bK[8][2];
#pragma unroll
            for (int p = 0; p < 4; ++p)
                LDSM4(bK[2 * p][0], bK[2 * p][1], bK[2 * p + 1][0], bK[2 * p + 1][1],
                      Ksb + koff + p * (16 * 68 * 4) + kk * 32);
#pragma unroll
            for (int j = 0; j < 8; ++j) mma_tf32(s[j], qf[kk], bK[j]);
        }

        // ---- mask + online softmax ----
        const bool diag = (kt == qb);
        float mx_lo = -1e30f, mx_hi = -1e30f;
#pragma unroll
        for (int j = 0; j < 8; ++j) {
#pragma unroll
            for (int e = 0; e < 2; ++e) {
                int col = j * 8 + 2 * r + e;
                float plo = s[j][e] * scale;
                float phi = s[j][2 + e] * scale;
                if (diag && col > row0 + g) plo = -1e30f;
                if (diag && col > row0 + 8 + g) phi = -1e30f;
                s[j][e] = plo;
                s[j][2 + e] = phi;
                mx_lo = fmaxf(mx_lo, plo);
                mx_hi = fmaxf(mx_hi, phi);
            }
        }
#pragma unroll
        for (int off = 1; off <= 2; off <<= 1) {
            mx_lo = fmaxf(mx_lo, __shfl_xor_sync(0xffffffffu, mx_lo, off));
            mx_hi = fmaxf(mx_hi, __shfl_xor_sync(0xffffffffu, mx_hi, off));
        }
        float mn_lo = fmaxf(m_lo, mx_lo);
        float mn_hi = fmaxf(m_hi, mx_hi);
        float sum_lo = 0.f, sum_hi = 0.f;
#pragma unroll
        for (int j = 0; j < 8; ++j) {
#pragma unroll
            for (int e = 0; e < 2; ++e) {
                s[j][e]     = __expf(s[j][e] - mn_lo);
                s[j][2 + e] = __expf(s[j][2 + e] - mn_hi);
                sum_lo += s[j][e];
                sum_hi += s[j][2 + e];
            }
        }
#pragma unroll
        for (int off = 1; off <= 2; off <<= 1) {
            sum_lo += __shfl_xor_sync(0xffffffffu, sum_lo, off);
            sum_hi += __shfl_xor_sync(0xffffffffu, sum_hi, off);
        }
        float al_lo = __expf(m_lo - mn_lo);
        float al_hi = __expf(m_hi - mn_hi);
        l_lo = l_lo * al_lo + sum_lo;
        l_hi = l_hi * al_hi + sum_hi;
        m_lo = mn_lo;
        m_hi = mn_hi;
#pragma unroll
        for (int j = 0; j < 8; ++j) {
            oacc[j][0] *= al_lo; oacc[j][1] *= al_lo;
            oacc[j][2] *= al_hi; oacc[j][3] *= al_hi;
        }

        // ---- P to tf32 ----
        unsigned pt[8][4];
#pragma unroll
        for (int j = 0; j < 8; ++j)
#pragma unroll
            for (int e = 0; e < 4; ++e) pt[j][e] = f2tf(s[j][e]);

        // ---- O += P V : A-frags via shuffles, B-frags via ldmatrix on Vt ----
        const int srcA = (lane & ~3) | (r >> 1);
        const int srcB = (lane & ~3) | (((r + 4) >> 1));
        const bool odd = (r & 1);
#pragma unroll
        for (int kk = 0; kk < 8; ++kk) {
            unsigned a[4];
            {
                unsigned t0 = __shfl_sync(0xffffffffu, pt[kk][0], srcA);
                unsigned t1 = __shfl_sync(0xffffffffu, pt[kk][1], srcA);
                unsigned t2 = __shfl_sync(0xffffffffu, pt[kk][0], srcB);
                unsigned t3 = __shfl_sync(0xffffffffu, pt[kk][1], srcB);
                a[0] = odd ? t1 : t0;
                a[2] = odd ? t3 : t2;
                t0 = __shfl_sync(0xffffffffu, pt[kk][2], srcA);
                t1 = __shfl_sync(0xffffffffu, pt[kk][3], srcA);
                t2 = __shfl_sync(0xffffffffu, pt[kk][2], srcB);
                t3 = __shfl_sync(0xffffffffu, pt[kk][3], srcB);
                a[1] = odd ? t1 : t0;
                a[3] = odd ? t3 : t2;
            }
            unsigned bV[8][2];
#pragma unroll
            for (int p = 0; p < 4; ++p)
                LDSM4(bV[2 * p][0], bV[2 * p][1], bV[2 * p + 1][0], bV[2 * p + 1][1],
                      Vtb + koff + p * (16 * 68 * 4) + kk * 32);
#pragma unroll
            for (int j = 0; j < 8; ++j) mma_tf32(oacc[j], a, bV[j]);
        }
        __syncthreads();
    }

    // ---- normalize + write ----
    float inv_lo = 1.f / l_lo;
    float inv_hi = 1.f / l_hi;
    int row_lo = qb * 64 + row0 + g;
#pragma unroll
    for (int j = 0; j < 8; ++j) {
        int n = h * HDIM + j * 8 + 2 * r;
        *(float2*)&y[(size_t)row_lo * DIM + n] =
            make_float2(oacc[j][0] * inv_lo, oacc[j][1] * inv_lo);
        *(float2*)&y[(size_t)(row_lo + 8) * DIM + n] =
            make_float2(oacc[j][2] * inv_hi, oacc[j][3] * inv_hi);
    }
}

// ---------------------------------------------------------------------------
extern "C" void kernel_launch(void* const* d_in, const int* in_sizes, int n_in,
                              void* d_out, int out_size)
{
    (void)in_sizes; (void)n_in; (void)out_size;
    const float* x      = (const float*)d_in[0];
    const float* w_attn = (const float*)d_in[1];
    const float* w_proj = (const float*)d_in[2];
    float* out = (float*)d_out;

    float* qkv_p = nullptr;
    float* y_p   = nullptr;
    cudaGetSymbolAddress((void**)&qkv_p, g_qkv);
    cudaGetSymbolAddress((void**)&y_p, g_y);

    const int gemm_smem = 4 * GTILE * (int)sizeof(float);   // 73728
    cudaFuncSetAttribute(gemm_tf32_lm, cudaFuncAttributeMaxDynamicSharedMemorySize, gemm_smem);

    {   // QKV: [4096,1024] x [3072,1024]^T -> [4096,3072]
        dim3 grid(3 * DIM / 128, SEQ / 128);
        gemm_tf32_lm<<<grid, 256, gemm_smem>>>(x, w_attn, qkv_p, SEQ, 3 * DIM, DIM);
    }
    {   // causal flash attention (64-query tiles)
        dim3 grid(SEQ / 64, NHEAD);
        attn_tf32<<<grid, 128>>>(qkv_p, y_p);
    }
    {   // proj: [4096,1024] x [1024,1024]^T -> out
        dim3 grid(DIM / 128, SEQ / 128);
        gemm_tf32_lm<<<grid, 256, gemm_smem>>>(y_p, w_proj, out, SEQ, DIM, DIM);
    }
}

// round 14
// speedup vs baseline: 1.8770x; 1.8770x over previous
#include <cuda_runtime.h>
#include <cstddef>
#include <cstdint>

#define SEQ 4096
#define DIM 1024
#define NHEAD 16
#define HDIM 64

__device__ float g_qkv[(size_t)SEQ * 3 * DIM];   // [T, 3D]
__device__ float g_y[(size_t)SEQ * DIM];         // [T, D]

__device__ __forceinline__ unsigned f2tf(float f) {
    unsigned u;
    asm("cvt.rna.tf32.f32 %0, %1;" : "=r"(u) : "f"(f));
    return u;
}
__device__ __forceinline__ unsigned bits2tf(unsigned b) {
    return f2tf(__uint_as_float(b));
}

__device__ __forceinline__ void mma_tf32(float c[4], const unsigned a[4], const unsigned b[2]) {
    asm volatile(
        "mma.sync.aligned.m16n8k8.row.col.f32.tf32.tf32.f32 "
        "{%0,%1,%2,%3}, {%4,%5,%6,%7}, {%8,%9}, {%0,%1,%2,%3};"
        : "+f"(c[0]), "+f"(c[1]), "+f"(c[2]), "+f"(c[3])
        : "r"(a[0]), "r"(a[1]), "r"(a[2]), "r"(a[3]), "r"(b[0]), "r"(b[1]));
}

__device__ __forceinline__ uint32_t smem_u32(const void* p) {
    return (uint32_t)__cvta_generic_to_shared(p);
}

__device__ __forceinline__ void cp16(void* smem_dst, const void* gsrc) {
    unsigned d = (unsigned)__cvta_generic_to_shared(smem_dst);
    asm volatile("cp.async.cg.shared.global [%0], [%1], 16;" :: "r"(d), "l"(gsrc) : "memory");
}
#define CP_COMMIT() asm volatile("cp.async.commit_group;" ::: "memory")
#define CP_WAIT1()  asm volatile("cp.async.wait_group 1;" ::: "memory")

// ldmatrix.x4 of b16 8x8 tiles == four 8x4 tf32 tiles in mma frag layout.
#define LDSM4(r0, r1, r2, r3, addr)                                              \
    asm volatile("ldmatrix.sync.aligned.m8n8.x4.shared.b16 {%0,%1,%2,%3}, [%4];" \
                 : "=r"(r0), "=r"(r1), "=r"(r2), "=r"(r3) : "r"(addr))

// ===========================================================================
// TF32 GEMM "NT": C[m][n] = sum_k A[m][k]*B[n][k]
// 128x128 tile, KT=32, 256 threads (8 warps, 2m x 4n), warp tile 64x32.
// cp.async double-buffered RAW fp32 smem (stride 36); fragments via
// ldmatrix.x4 on the raw bits; cvt.rna.tf32 applied per-register after LDSM
// (numerically identical to cvt-at-store). launch_bounds(256,2) -> 2 CTA/SM.
// Dynamic smem: 4 * 128*36 * 4B = 73728 bytes.
// ===========================================================================
#define GST 36
#define GTILE (128 * GST)

__global__ __launch_bounds__(256, 2) void gemm_tf32_lm(const float* __restrict__ A,
                                                       const float* __restrict__ B,
                                                       float* __restrict__ C,
                                                       int M, int N, int K)
{
    extern __shared__ float sm[];  // [2][A 128*36 | B 128*36]

    const int tid  = threadIdx.x;
    const int lane = tid & 31;
    const int warp = tid >> 5;
    const int wm = warp & 1;
    const int wn = warp >> 1;
    const int bm = blockIdx.y * 128;
    const int bn = blockIdx.x * 128;
    const int g = lane >> 2;
    const int r = lane & 3;

    const int srow = tid >> 3;     // 0..31 (+32/step)
    const int sc4  = tid & 7;

    auto stage = [&](int kt, int buf) {
        const float* Ap = A + (size_t)(bm + srow) * K + kt * 32 + sc4 * 4;
        const float* Bp = B + (size_t)(bn + srow) * K + kt * 32 + sc4 * 4;
        float* Ad = sm + buf * 2 * GTILE;
        float* Bd = Ad + GTILE;
#pragma unroll
        for (int t = 0; t < 4; ++t) {
            int row = srow + 32 * t;
            cp16(&Ad[row * GST + sc4 * 4], Ap + (size_t)(32 * t) * K);
            cp16(&Bd[row * GST + sc4 * 4], Bp + (size_t)(32 * t) * K);
        }
    };

    float acc[4][4][4];
#pragma unroll
    for (int mi = 0; mi < 4; ++mi)
#pragma unroll
        for (int nj = 0; nj < 4; ++nj)
#pragma unroll
            for (int e = 0; e < 4; ++e) acc[mi][nj][e] = 0.f;

    // Per-lane ldmatrix base offsets (bytes) within a buffer.
    const uint32_t aoff =
        (uint32_t)(((wm * 64 + ((lane >> 3) & 1) * 8 + (lane & 7)) * GST + (lane >> 4) * 4) * 4);
    const uint32_t boff =
        (uint32_t)(((wn * 32 + (lane >> 4) * 8 + (lane & 7)) * GST + ((lane >> 3) & 1) * 4) * 4);

    const int nt = K / 32;
    stage(0, 0);
    CP_COMMIT();

    for (int kt = 0; kt < nt; ++kt) {
        const int buf = kt & 1;
        if (kt + 1 < nt) stage(kt + 1, buf ^ 1);
        CP_COMMIT();
        CP_WAIT1();
        __syncthreads();

        const uint32_t Abase = smem_u32(sm + buf * 2 * GTILE);
        const uint32_t Bbase = Abase + GTILE * 4;

#pragma unroll
        for (int kk = 0; kk < 4; ++kk) {
            const uint32_t ko = kk * 32;
            unsigned af[4][4];
#pragma unroll
            for (int mi = 0; mi < 4; ++mi)
                LDSM4(af[mi][0], af[mi][1], af[mi][2], af[mi][3],
                      Abase + aoff + mi * (16 * GST * 4) + ko);
            unsigned bf[4][2];
            LDSM4(bf[0][0], bf[0][1], bf[1][0], bf[1][1], Bbase + boff + ko);
            LDSM4(bf[2][0], bf[2][1], bf[3][0], bf[3][1],
                  Bbase + boff + 16 * GST * 4 + ko);
            // tf32 rounding on raw bits (same numerics as cvt-at-store)
#pragma unroll
            for (int mi = 0; mi < 4; ++mi)
#pragma unroll
                for (int e = 0; e < 4; ++e) af[mi][e] = bits2tf(af[mi][e]);
#pragma unroll
            for (int nj = 0; nj < 4; ++nj) {
                bf[nj][0] = bits2tf(bf[nj][0]);
                bf[nj][1] = bits2tf(bf[nj][1]);
            }
#pragma unroll
            for (int mi = 0; mi < 4; ++mi)
#pragma unroll
                for (int nj = 0; nj < 4; ++nj)
                    mma_tf32(acc[mi][nj], af[mi], bf[nj]);
        }
        __syncthreads();
    }

    // Epilogue
#pragma unroll
    for (int mi = 0; mi < 4; ++mi) {
        int m = bm + wm * 64 + mi * 16 + g;
#pragma unroll
        for (int nj = 0; nj < 4; ++nj) {
            int n = bn + wn * 32 + nj * 8 + 2 * r;
            *(float2*)&C[(size_t)m * N + n]       = make_float2(acc[mi][nj][0], acc[mi][nj][1]);
            *(float2*)&C[(size_t)(m + 8) * N + n] = make_float2(acc[mi][nj][2], acc[mi][nj][3]);
        }
    }
}

// ===========================================================================
// TF32 flash attention, causal (R6 structure: 64-query tile, 4 warps).
// Q and K fragments via ldmatrix.x4 on the unchanged stride-68 K layout.
// V stays row-major (Vs[token][d], stride 72) with scalar PV frag loads
// (conflict-free). P stays in registers via shuffles. Heavy blocks first.
// ===========================================================================
__global__ __launch_bounds__(128) void attn_tf32(const float* __restrict__ qkv,
                                                 float* __restrict__ y)
{
    __shared__ unsigned Ks[64][68];
    __shared__ unsigned Vs[64][72];

    const int tid  = threadIdx.x;
    const int lane = tid & 31;
    const int warp = tid >> 5;
    const int qb = gridDim.x - 1 - blockIdx.x;   // heavy blocks first
    const int h  = blockIdx.y;
    const int g = lane >> 2;
    const int r = lane & 3;
    const int row0 = warp * 16;
    const float scale = 0.125f;

    const uint32_t Ksb = smem_u32(&Ks[0][0]);
    // A-type lane offset (Q fragments), stride 68
    const uint32_t qoff =
        (uint32_t)(((row0 + ((lane >> 3) & 1) * 8 + (lane & 7)) * 68 + (lane >> 4) * 4) * 4);
    // B-type lane offset (K fragments), stride 68
    const uint32_t koff =
        (uint32_t)((((lane >> 4) * 8 + (lane & 7)) * 68 + ((lane >> 3) & 1) * 4) * 4);

    // ---- Stage Q (tf32) into Ks, pull fragments via ldmatrix ----
#pragma unroll
    for (int t = 0; t < 8; ++t) {
        int idx = tid + t * 128;
        int row = idx >> 4;
        int c4  = idx & 15;
        float4 v = *(const float4*)&qkv[(size_t)(qb * 64 + row) * (3 * DIM) + h * HDIM + c4 * 4];
        *(uint4*)&Ks[row][c4 * 4] = make_uint4(f2tf(v.x), f2tf(v.y), f2tf(v.z), f2tf(v.w));
    }
    __syncthreads();

    unsigned qf[8][4];
#pragma unroll
    for (int kk = 0; kk < 8; ++kk)
        LDSM4(qf[kk][0], qf[kk][1], qf[kk][2], qf[kk][3], Ksb + qoff + kk * 32);
    __syncthreads();

    float oacc[8][4];
#pragma unroll
    for (int j = 0; j < 8; ++j)
#pragma unroll
        for (int e = 0; e < 4; ++e) oacc[j][e] = 0.f;

    float m_lo = -1e30f, m_hi = -1e30f, l_lo = 0.f, l_hi = 0.f;

    for (int kt = 0; kt <= qb; ++kt) {
        // ---- Stage K [token][d] and V [token][d] (tf32) ----
#pragma unroll
        for (int t = 0; t < 8; ++t) {
            int idx = tid + t * 128;
            int row = idx >> 4;
            int c4  = idx & 15;
            size_t base = (size_t)(kt * 64 + row) * (3 * DIM) + h * HDIM + c4 * 4;
            float4 kv = *(const float4*)&qkv[base + DIM];
            *(uint4*)&Ks[row][c4 * 4] = make_uint4(f2tf(kv.x), f2tf(kv.y), f2tf(kv.z), f2tf(kv.w));
            float4 vv = *(const float4*)&qkv[base + 2 * DIM];
            *(uint4*)&Vs[row][c4 * 4] = make_uint4(f2tf(vv.x), f2tf(vv.y), f2tf(vv.z), f2tf(vv.w));
        }
        __syncthreads();

        // ---- S = Q K^T : K frags via ldmatrix ----
        float s[8][4];
#pragma unroll
        for (int j = 0; j < 8; ++j)
#pragma unroll
            for (int e = 0; e < 4; ++e) s[j][e] = 0.f;

#pragma unroll
        for (int kk = 0; kk < 8; ++kk) {
            unsigned bK[8][2];
#pragma unroll
            for (int p = 0; p < 4; ++p)
                LDSM4(bK[2 * p][0], bK[2 * p][1], bK[2 * p + 1][0], bK[2 * p + 1][1],
                      Ksb + koff + p * (16 * 68 * 4) + kk * 32);
#pragma unroll
            for (int j = 0; j < 8; ++j) mma_tf32(s[j], qf[kk], bK[j]);
        }

        // ---- mask + online softmax ----
        const bool diag = (kt == qb);
        float mx_lo = -1e30f, mx_hi = -1e30f;
#pragma unroll
        for (int j = 0; j < 8; ++j) {
#pragma unroll
            for (int e = 0; e < 2; ++e) {
                int col = j * 8 + 2 * r + e;
                float plo = s[j][e] * scale;
                float phi = s[j][2 + e] * scale;
                if (diag && col > row0 + g) plo = -1e30f;
                if (diag && col > row0 + 8 + g) phi = -1e30f;
                s[j][e] = plo;
                s[j][2 + e] = phi;
                mx_lo = fmaxf(mx_lo, plo);
                mx_hi = fmaxf(mx_hi, phi);
            }
        }
#pragma unroll
        for (int off = 1; off <= 2; off <<= 1) {
            mx_lo = fmaxf(mx_lo, __shfl_xor_sync(0xffffffffu, mx_lo, off));
            mx_hi = fmaxf(mx_hi, __shfl_xor_sync(0xffffffffu, mx_hi, off));
        }
        float mn_lo = fmaxf(m_lo, mx_lo);
        float mn_hi = fmaxf(m_hi, mx_hi);
        float sum_lo = 0.f, sum_hi = 0.f;
#pragma unroll
        for (int j = 0; j < 8; ++j) {
#pragma unroll
            for (int e = 0; e < 2; ++e) {
                s[j][e]     = __expf(s[j][e] - mn_lo);
                s[j][2 + e] = __expf(s[j][2 + e] - mn_hi);
                sum_lo += s[j][e];
                sum_hi += s[j][2 + e];
            }
        }
#pragma unroll
        for (int off = 1; off <= 2; off <<= 1) {
            sum_lo += __shfl_xor_sync(0xffffffffu, sum_lo, off);
            sum_hi += __shfl_xor_sync(0xffffffffu, sum_hi, off);
        }
        float al_lo = __expf(m_lo - mn_lo);
        float al_hi = __expf(m_hi - mn_hi);
        l_lo = l_lo * al_lo + sum_lo;
        l_hi = l_hi * al_hi + sum_hi;
        m_lo = mn_lo;
        m_hi = mn_hi;
#pragma unroll
        for (int j = 0; j < 8; ++j) {
            oacc[j][0] *= al_lo; oacc[j][1] *= al_lo;
            oacc[j][2] *= al_hi; oacc[j][3] *= al_hi;
        }

        // ---- P to tf32 ----
        unsigned pt[8][4];
#pragma unroll
        for (int j = 0; j < 8; ++j)
#pragma unroll
            for (int e = 0; e < 4; ++e) pt[j][e] = f2tf(s[j][e]);

        // ---- O += P V : A-frags via shuffles, V frags scalar (conflict-free) ----
        const int srcA = (lane & ~3) | (r >> 1);
        const int srcB = (lane & ~3) | (((r + 4) >> 1));
        const bool odd = (r & 1);
#pragma unroll
        for (int kk = 0; kk < 8; ++kk) {
            unsigned a[4];
            {
                unsigned t0 = __shfl_sync(0xffffffffu, pt[kk][0], srcA);
                unsigned t1 = __shfl_sync(0xffffffffu, pt[kk][1], srcA);
                unsigned t2 = __shfl_sync(0xffffffffu, pt[kk][0], srcB);
                unsigned t3 = __shfl_sync(0xffffffffu, pt[kk][1], srcB);
                a[0] = odd ? t1 : t0;
                a[2] = odd ? t3 : t2;
                t0 = __shfl_sync(0xffffffffu, pt[kk][2], srcA);
                t1 = __shfl_sync(0xffffffffu, pt[kk][3], srcA);
                t2 = __shfl_sync(0xffffffffu, pt[kk][2], srcB);
                t3 = __shfl_sync(0xffffffffu, pt[kk][3], srcB);
                a[1] = odd ? t1 : t0;
                a[3] = odd ? t3 : t2;
            }
#pragma unroll
            for (int j = 0; j < 8; ++j) {
                unsigned bV[2];
                bV[0] = Vs[kk * 8 + r][j * 8 + g];
                bV[1] = Vs[kk * 8 + r + 4][j * 8 + g];
                mma_tf32(oacc[j], a, bV);
            }
        }
        __syncthreads();
    }

    // ---- normalize + write ----
    float inv_lo = 1.f / l_lo;
    float inv_hi = 1.f / l_hi;
    int row_lo = qb * 64 + row0 + g;
#pragma unroll
    for (int j = 0; j < 8; ++j) {
        int n = h * HDIM + j * 8 + 2 * r;
        *(float2*)&y[(size_t)row_lo * DIM + n] =
            make_float2(oacc[j][0] * inv_lo, oacc[j][1] * inv_lo);
        *(float2*)&y[(size_t)(row_lo + 8) * DIM + n] =
            make_float2(oacc[j][2] * inv_hi, oacc[j][3] * inv_hi);
    }
}

// ---------------------------------------------------------------------------
extern "C" void kernel_launch(void* const* d_in, const int* in_sizes, int n_in,
                              void* d_out, int out_size)
{
    (void)in_sizes; (void)n_in; (void)out_size;
    const float* x      = (const float*)d_in[0];
    const float* w_attn = (const float*)d_in[1];
    const float* w_proj = (const float*)d_in[2];
    float* out = (float*)d_out;

    float* qkv_p = nullptr;
    float* y_p   = nullptr;
    cudaGetSymbolAddress((void**)&qkv_p, g_qkv);
    cudaGetSymbolAddress((void**)&y_p, g_y);

    const int gemm_smem = 4 * GTILE * (int)sizeof(float);   // 73728
    cudaFuncSetAttribute(gemm_tf32_lm, cudaFuncAttributeMaxDynamicSharedMemorySize, gemm_smem);

    {   // QKV: [4096,1024] x [3072,1024]^T -> [4096,3072]
        dim3 grid(3 * DIM / 128, SEQ / 128);
        gemm_tf32_lm<<<grid, 256, gemm_smem>>>(x, w_attn, qkv_p, SEQ, 3 * DIM, DIM);
    }
    {   // causal flash attention (64-query tiles)
        dim3 grid(SEQ / 64, NHEAD);
        attn_tf32<<<grid, 128>>>(qkv_p, y_p);
    }
    {   // proj: [4096,1024] x [1024,1024]^T -> out
        dim3 grid(DIM / 128, SEQ / 128);
        gemm_tf32_lm<<<grid, 256, gemm_smem>>>(y_p, w_proj, out, SEQ, DIM, DIM);
    }
}